// round 10
// baseline (speedup 1.0000x reference)
#include <cuda_runtime.h>
#include <cuda_bf16.h>
#include <mma.h>
#include <math.h>
#include <stdint.h>

using namespace nvcuda;

#define NN 50000
#define NEDGE 800000
#define F 128
#define SCAN_T 1024
#define CHUNK ((NN + SCAN_T - 1) / SCAN_T)

// ---- scratch (static device globals; no allocation anywhere) ----
__device__ float g_h[(size_t)NN * F];     // transformed features
__device__ float g_x2[(size_t)NN * F];    // layer-2 input
__device__ float g_as[NN * 8];            // alpha_src per node/head
__device__ float g_ad[NN * 8];            // alpha_dst per node/head
__device__ float g_gmax[8];               // global per-head max of g_as
__device__ int   g_cnt[NN];               // in-degree counts
__device__ int   g_off[NN + 1];           // CSR offsets (by dst)
__device__ int   g_cur[NN];               // scatter cursors
__device__ int   g_csrc[NEDGE];           // CSR src indices

__device__ __forceinline__ float lrelu(float v) { return v >= 0.f ? v : 0.2f * v; }

__device__ __forceinline__ void atomicMaxF(float* a, float v) {
    if (v >= 0.f) atomicMax((int*)a, __float_as_int(v));
    else          atomicMin((unsigned int*)a, __float_as_uint(v));
}
__device__ __forceinline__ void atomicMaxFs(float* a, float v) {  // shared-mem variant
    if (v >= 0.f) atomicMax((int*)a, __float_as_int(v));
    else          atomicMin((unsigned int*)a, __float_as_uint(v));
}

// ================= CSR build (once per launch, shared by both layers) ========
__global__ void zero_cnt() {
    int i = blockIdx.x * blockDim.x + threadIdx.x;
    if (i < NN) g_cnt[i] = 0;
}

__global__ void count_edges(const int* __restrict__ ei) {
    int e = blockIdx.x * blockDim.x + threadIdx.x;
    if (e < NEDGE) atomicAdd(&g_cnt[ei[NEDGE + e]], 1);
}

__global__ void scan_offsets() {
    __shared__ int partial[SCAN_T];
    int t = threadIdx.x;
    int start = t * CHUNK;
    int end = min(start + CHUNK, NN);
    int s = 0;
    for (int i = start; i < end; i++) s += g_cnt[i];
    partial[t] = s;
    __syncthreads();
    for (int off = 1; off < SCAN_T; off <<= 1) {
        int v = (t >= off) ? partial[t - off] : 0;
        __syncthreads();
        partial[t] += v;
        __syncthreads();
    }
    int run = partial[t] - s;
    for (int i = start; i < end; i++) {
        g_off[i] = run;
        g_cur[i] = run;
        run += g_cnt[i];
    }
    if (t == SCAN_T - 1) g_off[NN] = partial[SCAN_T - 1];
}

__global__ void scatter_edges(const int* __restrict__ ei) {
    int e = blockIdx.x * blockDim.x + threadIdx.x;
    if (e >= NEDGE) return;
    int s = ei[e], d = ei[NEDGE + e];
    int pos = atomicAdd(&g_cur[d], 1);
    g_csrc[pos] = s;
}

// ================= wmma bf16-split GEMM: h = x @ W, fused alpha + gmax =======
// 3-term split for fp32 accuracy: xh*wh + xh*wl + xl*wh, fp32 accumulate.
// Block: 256 threads (8 warps), tile 128 rows x 128 cols, K chunked at 64.
// SMEM (dynamic): [0,16K) Ah bf16 128x64; [16K,32K) Al; [32K,48K) Bh bf16 64x128;
// [48K,64K) Bl; epilogue reuses [0,64K) as fp32 D[128][128].
// [64K..) asr(512) adr(512) red(32).
#define SMS_AH 0
#define SMS_AL 16384
#define SMS_BH 32768
#define SMS_BL 49152
#define SMS_AS 65536
#define SMS_AD 66048
#define SMS_RED 66560
#define GEMM_SMEM 66688

__global__ void __launch_bounds__(256, 1)
gemm_wmma(const float* __restrict__ xin, int use_x2,
          const float* __restrict__ W,
          const float* __restrict__ asr,
          const float* __restrict__ adr)
{
    extern __shared__ char sm[];
    const float* x = use_x2 ? g_x2 : xin;
    __nv_bfloat16* Ah = (__nv_bfloat16*)(sm + SMS_AH);
    __nv_bfloat16* Al = (__nv_bfloat16*)(sm + SMS_AL);
    __nv_bfloat16* Bh = (__nv_bfloat16*)(sm + SMS_BH);
    __nv_bfloat16* Bl = (__nv_bfloat16*)(sm + SMS_BL);
    float* sa  = (float*)(sm + SMS_AS);
    float* sd  = (float*)(sm + SMS_AD);
    float* red = (float*)(sm + SMS_RED);

    int tid = threadIdx.x, warp = tid >> 5;
    int row0 = blockIdx.x * 128;

    if (tid < 128) { sa[tid] = asr[tid]; sd[tid] = adr[tid]; }
    if (tid < 8) red[tid] = -INFINITY;

    wmma::fragment<wmma::accumulator, 16, 16, 16, float> acc[8];
#pragma unroll
    for (int nf = 0; nf < 8; nf++) wmma::fill_fragment(acc[nf], 0.f);

    for (int kb = 0; kb < 128; kb += 64) {
        __syncthreads();
        // stage A chunk: 128 rows x 64 k, hi/lo bf16 split
        for (int i = tid; i < 2048; i += 256) {      // float4 units
            int r = i >> 4, c4 = i & 15;
            int row = row0 + r;
            float4 v = make_float4(0.f, 0.f, 0.f, 0.f);
            if (row < NN) v = *(const float4*)(x + (size_t)row * 128 + kb + c4 * 4);
            float vv[4] = {v.x, v.y, v.z, v.w};
            __nv_bfloat16 h4[4], l4[4];
#pragma unroll
            for (int q = 0; q < 4; q++) {
                h4[q] = __float2bfloat16_rn(vv[q]);
                l4[q] = __float2bfloat16_rn(vv[q] - __bfloat162float(h4[q]));
            }
            int base = r * 64 + c4 * 4;
            *(ulonglong1*)(Ah + base) = *(ulonglong1*)h4;
            *(ulonglong1*)(Al + base) = *(ulonglong1*)l4;
        }
        // stage B chunk: 64 k-rows x 128 n, hi/lo bf16 split
        for (int i = tid; i < 2048; i += 256) {
            int kk = i >> 5, n4 = i & 31;
            float4 v = *(const float4*)(W + (size_t)(kb + kk) * 128 + n4 * 4);
            float vv[4] = {v.x, v.y, v.z, v.w};
            __nv_bfloat16 h4[4], l4[4];
#pragma unroll
            for (int q = 0; q < 4; q++) {
                h4[q] = __float2bfloat16_rn(vv[q]);
                l4[q] = __float2bfloat16_rn(vv[q] - __bfloat162float(h4[q]));
            }
            int base = kk * 128 + n4 * 4;
            *(ulonglong1*)(Bh + base) = *(ulonglong1*)h4;
            *(ulonglong1*)(Bl + base) = *(ulonglong1*)l4;
        }
        __syncthreads();

#pragma unroll
        for (int ks = 0; ks < 4; ks++) {
            wmma::fragment<wmma::matrix_a, 16, 16, 16, __nv_bfloat16, wmma::row_major> afh, afl;
            wmma::load_matrix_sync(afh, Ah + (warp * 16) * 64 + ks * 16, 64);
            wmma::load_matrix_sync(afl, Al + (warp * 16) * 64 + ks * 16, 64);
#pragma unroll
            for (int nf = 0; nf < 8; nf++) {
                wmma::fragment<wmma::matrix_b, 16, 16, 16, __nv_bfloat16, wmma::row_major> bfh, bfl;
                wmma::load_matrix_sync(bfh, Bh + (ks * 16) * 128 + nf * 16, 128);
                wmma::load_matrix_sync(bfl, Bl + (ks * 16) * 128 + nf * 16, 128);
                wmma::mma_sync(acc[nf], afh, bfh, acc[nf]);
                wmma::mma_sync(acc[nf], afh, bfl, acc[nf]);
                wmma::mma_sync(acc[nf], afl, bfh, acc[nf]);
            }
        }
    }
    __syncthreads();   // done reading bf16 staging; reuse as fp32 D tile

    float* D = (float*)sm;   // 128 x 128 fp32 = 64 KB
#pragma unroll
    for (int nf = 0; nf < 8; nf++)
        wmma::store_matrix_sync(D + (warp * 16) * 128 + nf * 16, acc[nf], 128,
                                wmma::mem_row_major);
    __syncthreads();

    // epilogue: threads 0..127 each own one row: write g_h, alphas, head max
    if (tid < 128) {
        int r = row0 + tid;
        if (r < NN) {
            const float* drow = D + tid * 128;
            float4* dst = (float4*)(g_h + (size_t)r * 128);
#pragma unroll
            for (int q = 0; q < 32; q++) dst[q] = ((const float4*)drow)[q];
            float lmax[8];
#pragma unroll
            for (int head = 0; head < 8; head++) {
                float ps = 0.f, pd = 0.f;
#pragma unroll
                for (int q = 0; q < 16; q++) {
                    float f = drow[head * 16 + q];
                    ps = fmaf(f, sa[head * 16 + q], ps);
                    pd = fmaf(f, sd[head * 16 + q], pd);
                }
                g_as[r * 8 + head] = ps;
                g_ad[r * 8 + head] = pd;
                lmax[head] = ps;
            }
#pragma unroll
            for (int head = 0; head < 8; head++)
                atomicMaxFs(&red[head], lmax[head]);
        }
    }
    __syncthreads();
    if (tid < 8) atomicMaxF(&g_gmax[tid], red[tid]);
}

// ================= init global max ==========================================
__global__ void init_gmax() {
    if (threadIdx.x < 8) g_gmax[threadIdx.x] = -INFINITY;
}

// ================= gather aggregation (warp per dst node) ====================
// lane owns 4 channels (head = lane>>2); register accumulation; no atomics.
__global__ void gat_gather(const float* __restrict__ bias,
                           float* __restrict__ out, int to_x2)
{
    int d    = (int)((blockIdx.x * (size_t)blockDim.x + threadIdx.x) >> 5);
    int lane = threadIdx.x & 31;
    if (d >= NN) return;
    int head = lane >> 2;

    float adv = g_ad[d * 8 + head];
    float mp  = lrelu(g_gmax[head] + adv);   // >= every edge score into d

    float w = __expf(lrelu(g_as[d * 8 + head] + adv) - mp);
    float4 hv = ((const float4*)(g_h + (size_t)d * 128))[lane];
    float denom = w;
    float4 acc = make_float4(w * hv.x, w * hv.y, w * hv.z, w * hv.w);

    int e  = g_off[d];
    int e1 = g_off[d + 1];
    for (; e + 3 < e1; e += 4) {
        int s0 = g_csrc[e];
        int s1 = g_csrc[e + 1];
        int s2 = g_csrc[e + 2];
        int s3 = g_csrc[e + 3];
        float a0 = g_as[s0 * 8 + head];
        float a1 = g_as[s1 * 8 + head];
        float a2 = g_as[s2 * 8 + head];
        float a3 = g_as[s3 * 8 + head];
        float4 h0 = ((const float4*)(g_h + (size_t)s0 * 128))[lane];
        float4 h1 = ((const float4*)(g_h + (size_t)s1 * 128))[lane];
        float4 h2 = ((const float4*)(g_h + (size_t)s2 * 128))[lane];
        float4 h3 = ((const float4*)(g_h + (size_t)s3 * 128))[lane];
        float w0 = __expf(lrelu(a0 + adv) - mp);
        float w1 = __expf(lrelu(a1 + adv) - mp);
        float w2 = __expf(lrelu(a2 + adv) - mp);
        float w3 = __expf(lrelu(a3 + adv) - mp);
        denom += (w0 + w1) + (w2 + w3);
        acc.x = fmaf(w0, h0.x, acc.x); acc.y = fmaf(w0, h0.y, acc.y);
        acc.z = fmaf(w0, h0.z, acc.z); acc.w = fmaf(w0, h0.w, acc.w);
        acc.x = fmaf(w1, h1.x, acc.x); acc.y = fmaf(w1, h1.y, acc.y);
        acc.z = fmaf(w1, h1.z, acc.z); acc.w = fmaf(w1, h1.w, acc.w);
        acc.x = fmaf(w2, h2.x, acc.x); acc.y = fmaf(w2, h2.y, acc.y);
        acc.z = fmaf(w2, h2.z, acc.z); acc.w = fmaf(w2, h2.w, acc.w);
        acc.x = fmaf(w3, h3.x, acc.x); acc.y = fmaf(w3, h3.y, acc.y);
        acc.z = fmaf(w3, h3.z, acc.z); acc.w = fmaf(w3, h3.w, acc.w);
    }
    for (; e < e1; e++) {
        int s0 = g_csrc[e];
        float a0 = g_as[s0 * 8 + head];
        float4 h0 = ((const float4*)(g_h + (size_t)s0 * 128))[lane];
        float w0 = __expf(lrelu(a0 + adv) - mp);
        denom += w0;
        acc.x = fmaf(w0, h0.x, acc.x); acc.y = fmaf(w0, h0.y, acc.y);
        acc.z = fmaf(w0, h0.z, acc.z); acc.w = fmaf(w0, h0.w, acc.w);
    }

    float inv = 1.f / (denom + 1e-16f);
    float4 b = ((const float4*)bias)[lane];
    float4 v;
    v.x = acc.x * inv + b.x; v.y = acc.y * inv + b.y;
    v.z = acc.z * inv + b.z; v.w = acc.w * inv + b.w;
    v.x = v.x > 0.f ? v.x : expm1f(v.x);
    v.y = v.y > 0.f ? v.y : expm1f(v.y);
    v.z = v.z > 0.f ? v.z : expm1f(v.z);
    v.w = v.w > 0.f ? v.w : expm1f(v.w);
    float4* dst = to_x2 ? (float4*)(g_x2 + (size_t)d * 128)
                        : (float4*)(out + (size_t)d * 128);
    dst[lane] = v;
}

extern "C" void kernel_launch(void* const* d_in, const int* in_sizes, int n_in,
                              void* d_out, int out_size) {
    const float* x   = (const float*)d_in[0];
    const int*   ei  = (const int*)d_in[1];
    const float* W1  = (const float*)d_in[2];
    const float* as1 = (const float*)d_in[3];
    const float* ad1 = (const float*)d_in[4];
    const float* b1  = (const float*)d_in[5];
    const float* W2  = (const float*)d_in[6];
    const float* as2 = (const float*)d_in[7];
    const float* ad2 = (const float*)d_in[8];
    const float* b2  = (const float*)d_in[9];
    float* out = (float*)d_out;

    static int smem_set = 0;
    if (!smem_set) {
        cudaFuncSetAttribute(gemm_wmma,
                             cudaFuncAttributeMaxDynamicSharedMemorySize,
                             GEMM_SMEM);
        smem_set = 1;
    }

    const int GB = (NN + 127) / 128;
    const int NB = (NN + 255) / 256;
    const int EB = (NEDGE + 255) / 256;
    const int AG = (int)(((size_t)NN * 32 + 255) / 256);

    // CSR build (shared by both layers)
    zero_cnt<<<NB, 256>>>();
    count_edges<<<EB, 256>>>(ei);
    scan_offsets<<<1, SCAN_T>>>();
    scatter_edges<<<EB, 256>>>(ei);

    for (int layer = 0; layer < 2; layer++) {
        init_gmax<<<1, 32>>>();
        gemm_wmma<<<GB, 256, GEMM_SMEM>>>(x, layer,
                                          layer ? W2 : W1,
                                          layer ? as2 : as1,
                                          layer ? ad2 : ad1);
        gat_gather<<<AG, 256>>>(layer ? b2 : b1, out, layer == 0);
    }
}

// round 11
// speedup vs baseline: 1.3622x; 1.3622x over previous
#include <cuda_runtime.h>
#include <cuda_bf16.h>
#include <mma.h>
#include <math.h>
#include <stdint.h>

using namespace nvcuda;

#define NN 50000
#define NEDGE 800000
#define F 128
#define SCAN_T 1024
#define CHUNK ((NN + SCAN_T - 1) / SCAN_T)

// padded leading dims: row stride ≡ 16B (mod 128B) -> conflict-free ldmatrix/STS
#define LDA 72     // A bf16: 144 B/row
#define LDB 136    // B bf16: 272 B/row
#define LDD 132    // D fp32: 528 B/row

// ---- scratch (static device globals; no allocation anywhere) ----
__device__ float g_h[(size_t)NN * F];     // transformed features
__device__ float g_x2[(size_t)NN * F];    // layer-2 input
__device__ float g_as[NN * 8];            // alpha_src per node/head
__device__ float g_ad[NN * 8];            // alpha_dst per node/head
__device__ float g_gmax[8];               // global per-head max of g_as
__device__ int   g_cnt[NN];               // in-degree counts
__device__ int   g_off[NN + 1];           // CSR offsets (by dst)
__device__ int   g_cur[NN];               // scatter cursors
__device__ int   g_csrc[NEDGE];           // CSR src indices

__device__ __forceinline__ float lrelu(float v) { return v >= 0.f ? v : 0.2f * v; }

__device__ __forceinline__ void atomicMaxF(float* a, float v) {
    if (v >= 0.f) atomicMax((int*)a, __float_as_int(v));
    else          atomicMin((unsigned int*)a, __float_as_uint(v));
}
__device__ __forceinline__ void atomicMaxFs(float* a, float v) {  // shared-mem variant
    if (v >= 0.f) atomicMax((int*)a, __float_as_int(v));
    else          atomicMin((unsigned int*)a, __float_as_uint(v));
}

// ================= CSR build (once per launch, shared by both layers) ========
__global__ void zero_cnt() {
    int i = blockIdx.x * blockDim.x + threadIdx.x;
    if (i < NN) g_cnt[i] = 0;
}

__global__ void count_edges(const int* __restrict__ ei) {
    int e = blockIdx.x * blockDim.x + threadIdx.x;
    if (e < NEDGE) atomicAdd(&g_cnt[ei[NEDGE + e]], 1);
}

__global__ void scan_offsets() {
    __shared__ int partial[SCAN_T];
    int t = threadIdx.x;
    int start = t * CHUNK;
    int end = min(start + CHUNK, NN);
    int s = 0;
    for (int i = start; i < end; i++) s += g_cnt[i];
    partial[t] = s;
    __syncthreads();
    for (int off = 1; off < SCAN_T; off <<= 1) {
        int v = (t >= off) ? partial[t - off] : 0;
        __syncthreads();
        partial[t] += v;
        __syncthreads();
    }
    int run = partial[t] - s;
    for (int i = start; i < end; i++) {
        g_off[i] = run;
        g_cur[i] = run;
        run += g_cnt[i];
    }
    if (t == SCAN_T - 1) g_off[NN] = partial[SCAN_T - 1];
}

__global__ void scatter_edges(const int* __restrict__ ei) {
    int e = blockIdx.x * blockDim.x + threadIdx.x;
    if (e >= NEDGE) return;
    int s = ei[e], d = ei[NEDGE + e];
    int pos = atomicAdd(&g_cur[d], 1);
    g_csrc[pos] = s;
}

// ================= wmma bf16-split GEMM: h = x @ W, fused alpha + gmax =======
// 3-term split for fp32 accuracy: xh*wh + xh*wl + xl*wh, fp32 accumulate.
// Block: 256 threads (8 warps), tile 128 rows x 128 cols, K chunked at 64.
// SMEM layout (dynamic), all padded strides:
//   Ah [128][72] bf16 = 18432   @ 0
//   Al                          @ 18432
//   Bh [64][136] bf16 = 17408   @ 36864
//   Bl                          @ 54272
//   (epilogue reuses [0, 67584) as fp32 D[128][132])
//   asr(512) @ 71680, adr(512) @ 72192, red(32) @ 72704. total 72736.
#define SMS_AH 0
#define SMS_AL 18432
#define SMS_BH 36864
#define SMS_BL 54272
#define SMS_AS 71680
#define SMS_AD 72192
#define SMS_RED 72704
#define GEMM_SMEM 72736

__global__ void __launch_bounds__(256)
gemm_wmma(const float* __restrict__ xin, int use_x2,
          const float* __restrict__ W,
          const float* __restrict__ asr,
          const float* __restrict__ adr)
{
    extern __shared__ char sm[];
    const float* x = use_x2 ? g_x2 : xin;
    __nv_bfloat16* Ah = (__nv_bfloat16*)(sm + SMS_AH);
    __nv_bfloat16* Al = (__nv_bfloat16*)(sm + SMS_AL);
    __nv_bfloat16* Bh = (__nv_bfloat16*)(sm + SMS_BH);
    __nv_bfloat16* Bl = (__nv_bfloat16*)(sm + SMS_BL);
    float* sa  = (float*)(sm + SMS_AS);
    float* sd  = (float*)(sm + SMS_AD);
    float* red = (float*)(sm + SMS_RED);

    int tid = threadIdx.x, warp = tid >> 5;
    int row0 = blockIdx.x * 128;

    if (tid < 128) { sa[tid] = asr[tid]; sd[tid] = adr[tid]; }
    if (tid < 8) red[tid] = -INFINITY;

    wmma::fragment<wmma::accumulator, 16, 16, 16, float> acc[8];
#pragma unroll
    for (int nf = 0; nf < 8; nf++) wmma::fill_fragment(acc[nf], 0.f);

    for (int kb = 0; kb < 128; kb += 64) {
        __syncthreads();
        // stage A chunk: 128 rows x 64 k, hi/lo bf16 split (padded LDA)
        for (int i = tid; i < 2048; i += 256) {      // float4 units
            int r = i >> 4, c4 = i & 15;
            int row = row0 + r;
            float4 v = make_float4(0.f, 0.f, 0.f, 0.f);
            if (row < NN) v = *(const float4*)(x + (size_t)row * 128 + kb + c4 * 4);
            float vv[4] = {v.x, v.y, v.z, v.w};
            __nv_bfloat16 h4[4], l4[4];
#pragma unroll
            for (int q = 0; q < 4; q++) {
                h4[q] = __float2bfloat16_rn(vv[q]);
                l4[q] = __float2bfloat16_rn(vv[q] - __bfloat162float(h4[q]));
            }
            int base = r * LDA + c4 * 4;
            *(ulonglong1*)(Ah + base) = *(ulonglong1*)h4;
            *(ulonglong1*)(Al + base) = *(ulonglong1*)l4;
        }
        // stage B chunk: 64 k-rows x 128 n, hi/lo bf16 split (padded LDB)
        for (int i = tid; i < 2048; i += 256) {
            int kk = i >> 5, n4 = i & 31;
            float4 v = *(const float4*)(W + (size_t)(kb + kk) * 128 + n4 * 4);
            float vv[4] = {v.x, v.y, v.z, v.w};
            __nv_bfloat16 h4[4], l4[4];
#pragma unroll
            for (int q = 0; q < 4; q++) {
                h4[q] = __float2bfloat16_rn(vv[q]);
                l4[q] = __float2bfloat16_rn(vv[q] - __bfloat162float(h4[q]));
            }
            int base = kk * LDB + n4 * 4;
            *(ulonglong1*)(Bh + base) = *(ulonglong1*)h4;
            *(ulonglong1*)(Bl + base) = *(ulonglong1*)l4;
        }
        __syncthreads();

#pragma unroll
        for (int ks = 0; ks < 4; ks++) {
            wmma::fragment<wmma::matrix_a, 16, 16, 16, __nv_bfloat16, wmma::row_major> afh, afl;
            wmma::load_matrix_sync(afh, Ah + (warp * 16) * LDA + ks * 16, LDA);
            wmma::load_matrix_sync(afl, Al + (warp * 16) * LDA + ks * 16, LDA);
#pragma unroll
            for (int nf = 0; nf < 8; nf++) {
                wmma::fragment<wmma::matrix_b, 16, 16, 16, __nv_bfloat16, wmma::row_major> bfh, bfl;
                wmma::load_matrix_sync(bfh, Bh + (ks * 16) * LDB + nf * 16, LDB);
                wmma::load_matrix_sync(bfl, Bl + (ks * 16) * LDB + nf * 16, LDB);
                wmma::mma_sync(acc[nf], afh, bfh, acc[nf]);
                wmma::mma_sync(acc[nf], afh, bfl, acc[nf]);
                wmma::mma_sync(acc[nf], afl, bfh, acc[nf]);
            }
        }
    }
    __syncthreads();   // done reading bf16 staging; reuse as fp32 D tile

    float* D = (float*)sm;   // 128 x LDD fp32 (padded)
#pragma unroll
    for (int nf = 0; nf < 8; nf++)
        wmma::store_matrix_sync(D + (warp * 16) * LDD + nf * 16, acc[nf], LDD,
                                wmma::mem_row_major);
    __syncthreads();

    // epilogue: threads 0..127 each own one row: write g_h, alphas, head max
    if (tid < 128) {
        int r = row0 + tid;
        if (r < NN) {
            const float* drow = D + tid * LDD;
            float4* dst = (float4*)(g_h + (size_t)r * 128);
#pragma unroll
            for (int q = 0; q < 32; q++) dst[q] = ((const float4*)drow)[q];
            float lmax[8];
#pragma unroll
            for (int head = 0; head < 8; head++) {
                float ps = 0.f, pd = 0.f;
#pragma unroll
                for (int q = 0; q < 16; q++) {
                    float f = drow[head * 16 + q];
                    ps = fmaf(f, sa[head * 16 + q], ps);
                    pd = fmaf(f, sd[head * 16 + q], pd);
                }
                g_as[r * 8 + head] = ps;
                g_ad[r * 8 + head] = pd;
                lmax[head] = ps;
            }
#pragma unroll
            for (int head = 0; head < 8; head++)
                atomicMaxFs(&red[head], lmax[head]);
        }
    }
    __syncthreads();
    if (tid < 8) atomicMaxF(&g_gmax[tid], red[tid]);
}

// ================= init global max ==========================================
__global__ void init_gmax() {
    if (threadIdx.x < 8) g_gmax[threadIdx.x] = -INFINITY;
}

// ================= gather aggregation (warp per dst node) ====================
// lane owns 4 channels (head = lane>>2); register accumulation; no atomics.
__global__ void gat_gather(const float* __restrict__ bias,
                           float* __restrict__ out, int to_x2)
{
    int d    = (int)((blockIdx.x * (size_t)blockDim.x + threadIdx.x) >> 5);
    int lane = threadIdx.x & 31;
    if (d >= NN) return;
    int head = lane >> 2;

    float adv = g_ad[d * 8 + head];
    float mp  = lrelu(g_gmax[head] + adv);   // >= every edge score into d

    float w = __expf(lrelu(g_as[d * 8 + head] + adv) - mp);
    float4 hv = ((const float4*)(g_h + (size_t)d * 128))[lane];
    float denom = w;
    float4 acc = make_float4(w * hv.x, w * hv.y, w * hv.z, w * hv.w);

    int e  = g_off[d];
    int e1 = g_off[d + 1];
    for (; e + 3 < e1; e += 4) {
        int s0 = g_csrc[e];
        int s1 = g_csrc[e + 1];
        int s2 = g_csrc[e + 2];
        int s3 = g_csrc[e + 3];
        float a0 = g_as[s0 * 8 + head];
        float a1 = g_as[s1 * 8 + head];
        float a2 = g_as[s2 * 8 + head];
        float a3 = g_as[s3 * 8 + head];
        float4 h0 = ((const float4*)(g_h + (size_t)s0 * 128))[lane];
        float4 h1 = ((const float4*)(g_h + (size_t)s1 * 128))[lane];
        float4 h2 = ((const float4*)(g_h + (size_t)s2 * 128))[lane];
        float4 h3 = ((const float4*)(g_h + (size_t)s3 * 128))[lane];
        float w0 = __expf(lrelu(a0 + adv) - mp);
        float w1 = __expf(lrelu(a1 + adv) - mp);
        float w2 = __expf(lrelu(a2 + adv) - mp);
        float w3 = __expf(lrelu(a3 + adv) - mp);
        denom += (w0 + w1) + (w2 + w3);
        acc.x = fmaf(w0, h0.x, acc.x); acc.y = fmaf(w0, h0.y, acc.y);
        acc.z = fmaf(w0, h0.z, acc.z); acc.w = fmaf(w0, h0.w, acc.w);
        acc.x = fmaf(w1, h1.x, acc.x); acc.y = fmaf(w1, h1.y, acc.y);
        acc.z = fmaf(w1, h1.z, acc.z); acc.w = fmaf(w1, h1.w, acc.w);
        acc.x = fmaf(w2, h2.x, acc.x); acc.y = fmaf(w2, h2.y, acc.y);
        acc.z = fmaf(w2, h2.z, acc.z); acc.w = fmaf(w2, h2.w, acc.w);
        acc.x = fmaf(w3, h3.x, acc.x); acc.y = fmaf(w3, h3.y, acc.y);
        acc.z = fmaf(w3, h3.z, acc.z); acc.w = fmaf(w3, h3.w, acc.w);
    }
    for (; e < e1; e++) {
        int s0 = g_csrc[e];
        float a0 = g_as[s0 * 8 + head];
        float4 h0 = ((const float4*)(g_h + (size_t)s0 * 128))[lane];
        float w0 = __expf(lrelu(a0 + adv) - mp);
        denom += w0;
        acc.x = fmaf(w0, h0.x, acc.x); acc.y = fmaf(w0, h0.y, acc.y);
        acc.z = fmaf(w0, h0.z, acc.z); acc.w = fmaf(w0, h0.w, acc.w);
    }

    float inv = 1.f / (denom + 1e-16f);
    float4 b = ((const float4*)bias)[lane];
    float4 v;
    v.x = acc.x * inv + b.x; v.y = acc.y * inv + b.y;
    v.z = acc.z * inv + b.z; v.w = acc.w * inv + b.w;
    v.x = v.x > 0.f ? v.x : expm1f(v.x);
    v.y = v.y > 0.f ? v.y : expm1f(v.y);
    v.z = v.z > 0.f ? v.z : expm1f(v.z);
    v.w = v.w > 0.f ? v.w : expm1f(v.w);
    float4* dst = to_x2 ? (float4*)(g_x2 + (size_t)d * 128)
                        : (float4*)(out + (size_t)d * 128);
    dst[lane] = v;
}

extern "C" void kernel_launch(void* const* d_in, const int* in_sizes, int n_in,
                              void* d_out, int out_size) {
    const float* x   = (const float*)d_in[0];
    const int*   ei  = (const int*)d_in[1];
    const float* W1  = (const float*)d_in[2];
    const float* as1 = (const float*)d_in[3];
    const float* ad1 = (const float*)d_in[4];
    const float* b1  = (const float*)d_in[5];
    const float* W2  = (const float*)d_in[6];
    const float* as2 = (const float*)d_in[7];
    const float* ad2 = (const float*)d_in[8];
    const float* b2  = (const float*)d_in[9];
    float* out = (float*)d_out;

    static int smem_set = 0;
    if (!smem_set) {
        cudaFuncSetAttribute(gemm_wmma,
                             cudaFuncAttributeMaxDynamicSharedMemorySize,
                             GEMM_SMEM);
        smem_set = 1;
    }

    const int GB = (NN + 127) / 128;
    const int NB = (NN + 255) / 256;
    const int EB = (NEDGE + 255) / 256;
    const int AG = (int)(((size_t)NN * 32 + 255) / 256);

    // CSR build (shared by both layers)
    zero_cnt<<<NB, 256>>>();
    count_edges<<<EB, 256>>>(ei);
    scan_offsets<<<1, SCAN_T>>>();
    scatter_edges<<<EB, 256>>>(ei);

    for (int layer = 0; layer < 2; layer++) {
        init_gmax<<<1, 32>>>();
        gemm_wmma<<<GB, 256, GEMM_SMEM>>>(x, layer,
                                          layer ? W2 : W1,
                                          layer ? as2 : as1,
                                          layer ? ad2 : ad1);
        gat_gather<<<AG, 256>>>(layer ? b2 : b1, out, layer == 0);
    }
}